// round 15
// baseline (speedup 1.0000x reference)
#include <cuda_runtime.h>
#include <cuda_bf16.h>
#include <cstdint>

#define NB     2048
#define NPAR   66048

// Scratch (device globals; allocation is forbidden)
__device__ __align__(16) float g_G [NB * 1024];            // X@Wk precomputed gates
__device__ __align__(16) float g_H [NB * 256];             // LSTM hidden outputs
__device__ __align__(16) __nv_bfloat16 g_Ah[NB * 256];     // X3 hi (bf16 split)
__device__ __align__(16) __nv_bfloat16 g_Al[NB * 256];     // X3 lo
__device__ __align__(16) __nv_bfloat16 g_Bh[(size_t)NPAR * 256]; // W^T hi, K-major [n][k]
__device__ __align__(16) __nv_bfloat16 g_Bl[(size_t)NPAR * 256]; // W^T lo

__device__ __forceinline__ float sigf(float x) {
    return __frcp_rn(1.0f + __expf(-x));
}

__device__ __forceinline__ float2 fma2(float2 a, float2 b, float2 c) {
    unsigned long long A, Bv, C, D;
    asm("mov.b64 %0, {%1,%2};" : "=l"(A)  : "f"(a.x), "f"(a.y));
    asm("mov.b64 %0, {%1,%2};" : "=l"(Bv) : "f"(b.x), "f"(b.y));
    asm("mov.b64 %0, {%1,%2};" : "=l"(C)  : "f"(c.x), "f"(c.y));
    asm("fma.rn.f32x2 %0, %1, %2, %3;" : "=l"(D) : "l"(A), "l"(Bv), "l"(C));
    float2 r;
    asm("mov.b64 {%0,%1}, %2;" : "=f"(r.x), "=f"(r.y) : "l"(D));
    return r;
}

// mov-free packed dual FMA: all operands already u64 register pairs
__device__ __forceinline__ unsigned long long fma2u(
    unsigned long long a, unsigned long long b, unsigned long long c) {
    unsigned long long d;
    asm("fma.rn.f32x2 %0, %1, %2, %3;" : "=l"(d) : "l"(a), "l"(b), "l"(c));
    return d;
}

__device__ __forceinline__ unsigned smem_u32(const void* p) {
    unsigned a;
    asm("{ .reg .u64 t; cvta.to.shared.u64 t, %1; cvt.u32.u64 %0, t; }" : "=r"(a) : "l"(p));
    return a;
}

// ---- async-copy / HMMA helpers ---------------------------------------------
#define SWZ(x) ((x) ^ (((x) >> 3) & 0x70))

#define CP_ASYNC16(dst, src) \
    asm volatile("cp.async.cg.shared.global [%0], [%1], 16;" :: "r"(dst), "l"(src) : "memory")
#define CP_COMMIT()  asm volatile("cp.async.commit_group;" ::: "memory")
#define CP_WAIT1()   asm volatile("cp.async.wait_group 1;" ::: "memory")
#define CP_WAIT0()   asm volatile("cp.async.wait_group 0;" ::: "memory")

#define LDSM_X4(r0, r1, r2, r3, addr) \
    asm volatile("ldmatrix.sync.aligned.m8n8.x4.shared.b16 {%0,%1,%2,%3}, [%4];" \
                 : "=r"(r0), "=r"(r1), "=r"(r2), "=r"(r3) : "r"(addr))

#define MMA16816(d, a, b0, b1) \
    asm volatile("mma.sync.aligned.m16n8k16.row.col.f32.bf16.bf16.f32 " \
                 "{%0,%1,%2,%3}, {%4,%5,%6,%7}, {%8,%9}, {%0,%1,%2,%3};" \
                 : "+f"((d)[0]), "+f"((d)[1]), "+f"((d)[2]), "+f"((d)[3]) \
                 : "r"((a)[0]), "r"((a)[1]), "r"((a)[2]), "r"((a)[3]), \
                   "r"(b0), "r"(b1))

// ===== Kernel WA: fused kW (blocks 0..2063) + kA (blocks 2064..2191) ========
#define KWA_NW (NPAR / 32)   // 2064

__global__ __launch_bounds__(256) void kWA(
    const float* __restrict__ Wout,
    const float* __restrict__ actions, const float* __restrict__ obs,
    const float* __restrict__ Wci, const float* __restrict__ vci,
    const float* __restrict__ gci, const float* __restrict__ bci,
    const float* __restrict__ Wcl, const float* __restrict__ bcl,
    const float* __restrict__ Win, const float* __restrict__ vin,
    const float* __restrict__ gin, const float* __restrict__ bin,
    const float* __restrict__ Wk)
{
    __shared__ float sm1[16 * 256];
    __shared__ float sm2[16 * 256];
    const int tid = threadIdx.x;

    if (blockIdx.x < KWA_NW) {
        // ------- kW part: transpose+split a 256k x 32n block -------
        float* sm = sm1;
        const int n0 = blockIdx.x * 32;
        #pragma unroll 4
        for (int it = 0; it < 32; it++) {
            const int idx = it * 256 + tid;
            const int k = idx >> 5, j = idx & 31;
            sm[j * 256 + (k ^ j)] = Wout[(size_t)k * NPAR + n0 + j];
        }
        __syncthreads();
        const int j  = tid & 31;
        const int kq = tid >> 5;
        __nv_bfloat16* ph = g_Bh + (size_t)(n0 + j) * 256 + kq * 32;
        __nv_bfloat16* pl = g_Bl + (size_t)(n0 + j) * 256 + kq * 32;
        #pragma unroll
        for (int kk = 0; kk < 32; kk++) {
            const float w = sm[j * 256 + ((kq * 32 + kk) ^ j)];
            const __nv_bfloat16 hi = __float2bfloat16(w);
            const __nv_bfloat16 lo = __float2bfloat16(w - __bfloat162float(hi));
            ph[kk] = hi;
            pl[kk] = lo;
        }
        return;
    }

    // ------- kA part -------
    const int r0 = (blockIdx.x - KWA_NW) * 16;

    { // t1 = actions @ Wci -> sm1[16][64]
        const int j = tid & 63, rr = tid >> 6;
        #pragma unroll
        for (int q = 0; q < 4; q++) {
            const int r = rr + q * 4;
            float acc = 0.f;
            #pragma unroll
            for (int k = 0; k < 16; k++)
                acc += actions[(r0 + r) * 16 + k] * Wci[k * 64 + j];
            sm1[r * 64 + j] = acc;
        }
    }
    __syncthreads();
    { // evonorm(groups=8) -> sm2[16][64]
        const int j = tid & 63, rr = tid >> 6;
        const float v = vci[j], g = gci[j], bb = bci[j];
        #pragma unroll
        for (int q = 0; q < 4; q++) {
            const int r = rr + q * 4;
            const float* row = &sm1[r * 64 + (j & ~7)];
            float s1 = 0.f, s2 = 0.f;
            #pragma unroll
            for (int e = 0; e < 8; e++) { float t = row[e]; s1 += t; s2 += t * t; }
            const float mean = s1 * 0.125f;
            const float var  = s2 * 0.125f - mean * mean;
            const float x = sm1[r * 64 + j];
            sm2[r * 64 + j] = x * sigf(v * x) * rsqrtf(var + 1e-5f) * g + bb;
        }
    }
    __syncthreads();
    { // x = a1 @ Wcl + bcl + obs -> sm1[16][64]
        const int j = tid & 63, rr = tid >> 6;
        const float bj = bcl[j];
        float acc[4];
        #pragma unroll
        for (int q = 0; q < 4; q++)
            acc[q] = bj + obs[(r0 + rr + q * 4) * 64 + j];
        for (int k = 0; k < 64; k++) {
            const float w = Wcl[k * 64 + j];
            #pragma unroll
            for (int q = 0; q < 4; q++)
                acc[q] += sm2[(rr + q * 4) * 64 + k] * w;
        }
        #pragma unroll
        for (int q = 0; q < 4; q++)
            sm1[(rr + q * 4) * 64 + j] = acc[q];
    }
    __syncthreads();
    { // t2 = x @ Win -> sm2[16][256]
        const int j = tid;
        float acc[16];
        #pragma unroll
        for (int r = 0; r < 16; r++) acc[r] = 0.f;
        for (int k = 0; k < 64; k++) {
            const float w = Win[k * 256 + j];
            #pragma unroll
            for (int r = 0; r < 16; r++) acc[r] += sm1[r * 64 + k] * w;
        }
        #pragma unroll
        for (int r = 0; r < 16; r++) sm2[r * 256 + j] = acc[r];
    }
    __syncthreads();
    { // evonorm(group size 8) -> sm1[16][256]
        const int j = tid;
        const float v = vin[j], g = gin[j], bb = bin[j];
        for (int r = 0; r < 16; r++) {
            const float* row = &sm2[r * 256 + (j & ~7)];
            float s1 = 0.f, s2 = 0.f;
            #pragma unroll
            for (int e = 0; e < 8; e++) { float t = row[e]; s1 += t; s2 += t * t; }
            const float mean = s1 * 0.125f;
            const float var  = s2 * 0.125f - mean * mean;
            const float x = sm2[r * 256 + j];
            sm1[r * 256 + j] = x * sigf(v * x) * rsqrtf(var + 1e-5f) * g + bb;
        }
    }
    __syncthreads();
    { // G = x_in @ Wk  (thread: 4 cols x 16 rows)
        const int c0 = tid * 4;
        float2 acc[16][2];
        #pragma unroll
        for (int r = 0; r < 16; r++) { acc[r][0] = make_float2(0.f,0.f); acc[r][1] = make_float2(0.f,0.f); }
        for (int k = 0; k < 256; k++) {
            const float4 w4 = *(const float4*)&Wk[k * 1024 + c0];
            const float2 wa = make_float2(w4.x, w4.y);
            const float2 wb = make_float2(w4.z, w4.w);
            #pragma unroll
            for (int r = 0; r < 16; r++) {
                const float x = sm1[r * 256 + k];
                const float2 xx = make_float2(x, x);
                acc[r][0] = fma2(wa, xx, acc[r][0]);
                acc[r][1] = fma2(wb, xx, acc[r][1]);
            }
        }
        #pragma unroll
        for (int r = 0; r < 16; r++) {
            float4 o;
            o.x = acc[r][0].x; o.y = acc[r][0].y; o.z = acc[r][1].x; o.w = acc[r][1].y;
            *(float4*)&g_G[(size_t)(r0 + r) * 1024 + c0] = o;
        }
    }
}

// ===== Kernel B: sequential LSTM, 8-CTA cluster =============================
// Thread (c, q): c = tid>>2 owns ONE column, q = tid&3 owns 64 k's.
// Partials reduced by 2 quad shfls (no smem round-trip, single syncthreads).
// Push: warp0 lanes 0-7, one release-arrive per source CTA (expected = 8).
__global__ void __launch_bounds__(512, 1) __cluster_dims__(8, 1, 1)
kB(const float* __restrict__ Wr, const float* __restrict__ vl_,
   const float* __restrict__ gl_, const float* __restrict__ bl_)
{
    __shared__ __align__(16) float s_hb[2][256];   // h buffers (remote-written)
    __shared__ __align__(16) float s_z[128];
    __shared__ __align__(16) float s_hout[32];
    __shared__ __align__(8)  unsigned long long s_mbar[2];

    const int tid = threadIdx.x;
    unsigned rank;
    asm("mov.u32 %0, %%cluster_ctarank;" : "=r"(rank));

    const int c  = tid >> 2;          // column 0..127
    const int q  = tid & 3;           // k-quarter 0..3
    const int gg = c >> 5;            // gate 0..3
    const int cc = c & 31;            // channel-in-CTA
    const int gcol = gg * 256 + (int)rank * 32 + cc;   // global gate column
    const int k0   = q * 64;

    // register-resident weights: 64 k's for one column, packed as 32 u64 pairs
    unsigned long long wv[32];
    #pragma unroll
    for (int p = 0; p < 32; p++) {
        const float w0 = Wr[(size_t)(k0 + 2*p)     * 1024 + gcol];
        const float w1 = Wr[(size_t)(k0 + 2*p + 1) * 1024 + gcol];
        asm("mov.b64 %0, {%1,%2};" : "=l"(wv[p]) : "f"(w0), "f"(w1));
    }

    // cell params for warp 0 (channel ch = rank*32 + lane)
    float vl = 0.f, gl = 0.f, bl = 0.f, cst = 0.f;
    if (tid < 32) {
        const int ch = (int)rank * 32 + tid;
        vl = vl_[ch]; gl = gl_[ch]; bl = bl_[ch];
    }

    // push addresses for warp0 lanes 0-7 (lane = dest CTA)
    unsigned r_h0 = 0, r_h1 = 0, r_b0 = 0, r_b1 = 0;
    if (tid < 8) {
        const unsigned d = (unsigned)tid;
        unsigned lh0 = smem_u32(&s_hb[0][rank * 32]);
        unsigned lh1 = smem_u32(&s_hb[1][rank * 32]);
        unsigned lb0 = smem_u32(&s_mbar[0]);
        unsigned lb1 = smem_u32(&s_mbar[1]);
        asm("mapa.shared::cluster.u32 %0, %1, %2;" : "=r"(r_h0) : "r"(lh0), "r"(d));
        asm("mapa.shared::cluster.u32 %0, %1, %2;" : "=r"(r_h1) : "r"(lh1), "r"(d));
        asm("mapa.shared::cluster.u32 %0, %1, %2;" : "=r"(r_b0) : "r"(lb0), "r"(d));
        asm("mapa.shared::cluster.u32 %0, %1, %2;" : "=r"(r_b1) : "r"(lb1), "r"(d));
    }

    if (tid == 0) {
        asm volatile("mbarrier.init.shared.b64 [%0], %1;" :: "r"(smem_u32(&s_mbar[0])), "r"(8u) : "memory");
        asm volatile("mbarrier.init.shared.b64 [%0], %1;" :: "r"(smem_u32(&s_mbar[1])), "r"(8u) : "memory");
    }
    if (tid < 256) { s_hb[0][tid] = 0.f; s_hb[1][tid] = 0.f; }
    __syncthreads();
    asm volatile("barrier.cluster.arrive.aligned;" ::: "memory");
    asm volatile("barrier.cluster.wait.aligned;"   ::: "memory");

    // initial push: zeros (h_{-1}) into buffer 1
    if (tid < 8) {
        #pragma unroll
        for (int i = 0; i < 8; i++)
            asm volatile("st.shared::cluster.v4.f32 [%0], {%1,%1,%1,%1};"
                         :: "r"(r_h1 + i * 16), "f"(0.f) : "memory");
        asm volatile("mbarrier.arrive.release.cluster.shared::cluster.b64 _, [%0];"
                     :: "r"(r_b1) : "memory");
    }

    unsigned par0 = 0u, par1 = 0u;
    float gt = (q == 0) ? g_G[gcol] : 0.f;   // prefetch step 0 (q==0 threads)

    for (int t = 0; t < NB; t++) {
        const int rb = (t + 1) & 1;      // buffer holding h_{t-1}
        const int wb = t & 1;            // buffer receiving h_t

        { // wait for all 8 source-CTA pushes of h_{t-1}
            const unsigned a = smem_u32(&s_mbar[rb]);
            const unsigned ph = rb ? par1 : par0;
            unsigned done;
            asm volatile(
                "{\n\t.reg .pred p;\n\t"
                "mbarrier.try_wait.parity.acquire.cluster.shared::cta.b64 p, [%1], %2;\n\t"
                "selp.b32 %0, 1, 0, p;\n\t}"
                : "=r"(done) : "r"(a), "r"(ph) : "memory");
            if (!done) {
                asm volatile(
                    "{\n\t.reg .pred P1;\n\t"
                    "WLB_%=:\n\t"
                    "mbarrier.try_wait.parity.acquire.cluster.shared::cta.b64 P1, [%0], %1, 0x989680;\n\t"
                    "@P1 bra.uni WDB_%=;\n\t"
                    "bra.uni WLB_%=;\n\t"
                    "WDB_%=:\n\t}"
                    :: "r"(a), "r"(ph) : "memory");
            }
            if (rb) par1 ^= 1u; else par0 ^= 1u;
        }

        // ---- GEMV: 1 col x 64 k per thread, quad-shfl reduce ----
        {
            const unsigned long long* hp =
                (const unsigned long long*)&s_hb[rb][k0];
            unsigned long long a0 = 0ULL, a1 = 0ULL, a2 = 0ULL, a3 = 0ULL;
            #pragma unroll
            for (int p = 0; p < 32; p += 4) {
                a0 = fma2u(wv[p],     hp[p],     a0);
                a1 = fma2u(wv[p + 1], hp[p + 1], a1);
                a2 = fma2u(wv[p + 2], hp[p + 2], a2);
                a3 = fma2u(wv[p + 3], hp[p + 3], a3);
            }
            float2 f0, f1, f2, f3;
            asm("mov.b64 {%0,%1}, %2;" : "=f"(f0.x), "=f"(f0.y) : "l"(a0));
            asm("mov.b64 {%0,%1}, %2;" : "=f"(f1.x), "=f"(f1.y) : "l"(a1));
            asm("mov.b64 {%0,%1}, %2;" : "=f"(f2.x), "=f"(f2.y) : "l"(a2));
            asm("mov.b64 {%0,%1}, %2;" : "=f"(f3.x), "=f"(f3.y) : "l"(a3));
            float sum = ((f0.x + f0.y) + (f1.x + f1.y)) +
                        ((f2.x + f2.y) + (f3.x + f3.y));
            sum += __shfl_xor_sync(0xffffffffu, sum, 1);
            sum += __shfl_xor_sync(0xffffffffu, sum, 2);
            if (q == 0) {
                s_z[c] = sum + gt;
                if (t + 1 < NB) gt = g_G[(size_t)(t + 1) * 1024 + gcol];
            }
        }
        __syncthreads();   // s_z complete

        // ---- cell: warp 0, lane = channel-in-CTA (fully local) ----
        if (tid < 32) {
            const float zi = s_z[tid];
            const float zf = s_z[32 + tid];
            const float zc = s_z[64 + tid];
            const float zo = s_z[96 + tid];

            float s1 = zc, s2 = zc * zc;
            s1 += __shfl_xor_sync(0xffffffffu, s1, 1);  s2 += __shfl_xor_sync(0xffffffffu, s2, 1);
            s1 += __shfl_xor_sync(0xffffffffu, s1, 2);  s2 += __shfl_xor_sync(0xffffffffu, s2, 2);
            s1 += __shfl_xor_sync(0xffffffffu, s1, 4);  s2 += __shfl_xor_sync(0xffffffffu, s2, 4);
            float mean = s1 * 0.125f;
            float var  = s2 * 0.125f - mean * mean;
            const float ecc = zc * sigf(vl * zc) * rsqrtf(var + 1e-5f) * gl + bl;

            cst = sigf(zf) * cst + sigf(zi) * ecc;

            s1 = cst; s2 = cst * cst;
            s1 += __shfl_xor_sync(0xffffffffu, s1, 1);  s2 += __shfl_xor_sync(0xffffffffu, s2, 1);
            s1 += __shfl_xor_sync(0xffffffffu, s1, 2);  s2 += __shfl_xor_sync(0xffffffffu, s2, 2);
            s1 += __shfl_xor_sync(0xffffffffu, s1, 4);  s2 += __shfl_xor_sync(0xffffffffu, s2, 4);
            mean = s1 * 0.125f;
            var  = s2 * 0.125f - mean * mean;
            const float ecn = cst * sigf(vl * cst) * rsqrtf(var + 1e-5f) * gl + bl;

            const float h = sigf(zo) * ecn;
            s_hout[tid] = h;
            __syncwarp();

            // push h_t: lane d -> dest CTA d (8 x st.v4 + 1 release-arrive)
            if (tid < 8) {
                const unsigned rh  = wb ? r_h1 : r_h0;
                const unsigned rbb = wb ? r_b1 : r_b0;
                #pragma unroll
                for (int i = 0; i < 8; i++) {
                    const float4 hv4 = *(const float4*)&s_hout[i * 4];
                    asm volatile("st.shared::cluster.v4.f32 [%0], {%1,%2,%3,%4};"
                                 :: "r"(rh + i * 16), "f"(hv4.x), "f"(hv4.y), "f"(hv4.z), "f"(hv4.w)
                                 : "memory");
                }
                asm volatile("mbarrier.arrive.release.cluster.shared::cluster.b64 _, [%0];"
                             :: "r"(rbb) : "memory");
            }
            g_H[(size_t)t * 256 + rank * 32 + tid] = h;
        }
    }

    asm volatile("barrier.cluster.arrive.aligned;" ::: "memory");
    asm volatile("barrier.cluster.wait.aligned;"   ::: "memory");
}

// ===== Kernel C: dense_0 + evonorm -> bf16 hi/lo split (g_Ah/g_Al) ==========
__global__ __launch_bounds__(256) void kC(
    const float* __restrict__ Wd0, const float* __restrict__ vd,
    const float* __restrict__ gd,  const float* __restrict__ bd)
{
    __shared__ float sm1[16 * 256];
    __shared__ float sm2[16 * 256];
    const int tid = threadIdx.x;
    const int r0  = blockIdx.x * 16;

    const float4* src = (const float4*)(g_H + (size_t)r0 * 256);
    for (int i = tid; i < 1024; i += 256)
        ((float4*)sm1)[i] = src[i];
    __syncthreads();

    const int j = tid;
    float acc[16];
    #pragma unroll
    for (int r = 0; r < 16; r++) acc[r] = 0.f;
    for (int k4 = 0; k4 < 64; k4++) {
        const int k = k4 * 4;
        const float w0 = Wd0[(k+0)*256 + j];
        const float w1 = Wd0[(k+1)*256 + j];
        const float w2 = Wd0[(k+2)*256 + j];
        const float w3 = Wd0[(k+3)*256 + j];
        #pragma unroll
        for (int r = 0; r < 16; r++) {
            const float4 x = *(const float4*)&sm1[r * 256 + k];
            acc[r] += x.x*w0 + x.y*w1 + x.z*w2 + x.w*w3;
        }
    }
    #pragma unroll
    for (int r = 0; r < 16; r++) sm2[r * 256 + j] = acc[r];
    __syncthreads();

    const float v = vd[j], g = gd[j], bb = bd[j];
    for (int r = 0; r < 16; r++) {
        const float* row = &sm2[r * 256 + (j & ~7)];
        float s1 = 0.f, s2 = 0.f;
        #pragma unroll
        for (int e = 0; e < 8; e++) { float t = row[e]; s1 += t; s2 += t * t; }
        const float mean = s1 * 0.125f;
        const float var  = s2 * 0.125f - mean * mean;
        const float x = sm2[r * 256 + j];
        const float y = x * sigf(v * x) * rsqrtf(var + 1e-5f) * g + bb;
        const __nv_bfloat16 hi = __float2bfloat16(y);
        const __nv_bfloat16 lo = __float2bfloat16(y - __bfloat162float(hi));
        g_Ah[(size_t)(r0 + r) * 256 + j] = hi;
        g_Al[(size_t)(r0 + r) * 256 + j] = lo;
    }
}

// ===== Kernel D: HMMA bf16 3-split GEMM, B smem-resident, A streamed ========
// CTA owns a 128-col B slice (all K, 128KB smem); 8 row tiles, A chunks
// double-buffered and software-pipelined ACROSS tiles (epilogue overlaps
// the next tile's A loads). Grid: x = 2 row halves, y = 516 col tiles.
#define KDB_SZ    131072
#define KDA_STAGE 32768
#define KD_SMEM   (KDB_SZ + 2 * KDA_STAGE)   // 196608

__device__ __forceinline__ void kd_loadB(uint32_t SB, int n0, int tid)
{
    #pragma unroll
    for (int c = 0; c < 4; c++) {
        #pragma unroll
        for (int sp = 0; sp < 2; sp++) {
            const __nv_bfloat16* gB = sp ? g_Bl : g_Bh;
            const uint32_t db = SB + c * 32768u + sp * 16384u;
            #pragma unroll
            for (int i = 0; i < 4; i++) {
                const int g2 = tid + i * 256;
                const int row = g2 >> 3, j = g2 & 7;
                CP_ASYNC16(db + SWZ(row * 128 + j * 16),
                           gB + (size_t)(n0 + row) * 256 + c * 64 + j * 8);
            }
        }
    }
    CP_COMMIT();
}

__device__ __forceinline__ void kd_loadA(uint32_t stage, int m0, int koff, int tid)
{
    #pragma unroll
    for (int sp = 0; sp < 2; sp++) {
        const __nv_bfloat16* gA = sp ? g_Al : g_Ah;
        const uint32_t db = stage + sp * 16384u;
        #pragma unroll
        for (int i = 0; i < 4; i++) {
            const int g2 = tid + i * 256;
            const int row = g2 >> 3, j = g2 & 7;
            CP_ASYNC16(db + SWZ(row * 128 + j * 16),
                       gA + (size_t)(m0 + row) * 256 + koff + j * 8);
        }
    }
    CP_COMMIT();
}

__device__ __forceinline__ void kd_compute(uint32_t Astage, uint32_t SB, int blk,
                                           uint32_t a_row, uint32_t a_kb,
                                           uint32_t b_row, uint32_t b_kb,
                                           float acc[4][4][4])
{
    #pragma unroll
    for (int split = 0; split < 3; split++) {
        const uint32_t Abase = Astage + (split == 2 ? 16384u : 0u);
        const uint32_t Bbase = SB + blk * 32768u + (split == 1 ? 16384u : 0u);
        #pragma unroll
        for (int ks = 0; ks < 4; ks++) {
            const uint32_t kk2 = (uint32_t)ks * 32;
            uint32_t af[4][4];
            #pragma unroll
            for (int mb = 0; mb < 4; mb++) {
                const uint32_t addr = Abase + SWZ((a_row + mb * 16) * 128 + kk2 + a_kb);
                LDSM_X4(af[mb][0], af[mb][1], af[mb][2], af[mb][3], addr);
            }
            uint32_t bfr[2][4];
            #pragma unroll
            for (int nb2 = 0; nb2 < 2; nb2++) {
                const uint32_t addr = Bbase + SWZ((b_row + nb2 * 16) * 128 + kk2 + b_kb);
                LDSM_X4(bfr[nb2][0], bfr[nb2][1], bfr[nb2][2], bfr[nb2][3], addr);
            }
            #pragma unroll
            for (int mb = 0; mb < 4; mb++) {
                MMA16816(acc[mb][0], af[mb], bfr[0][0], bfr[0][1]);
                MMA16816(acc[mb][1], af[mb], bfr[0][2], bfr[0][3]);
                MMA16816(acc[mb][2], af[mb], bfr[1][0], bfr[1][1]);
                MMA16816(acc[mb][3], af[mb], bfr[1][2], bfr[1][3]);
            }
        }
    }
}

__global__ void __launch_bounds__(256)
kD(const float* __restrict__ bout, float* __restrict__ out)
{
    extern __shared__ __align__(1024) char smem[];
    const uint32_t SB  = smem_u32(smem);
    const uint32_t SA0 = SB + KDB_SZ;
    const uint32_t SA1 = SA0 + KDA_STAGE;
    const int tid = threadIdx.x;
    const int wid = tid >> 5, lane = tid & 31;
    const int warp_m = wid & 1;
    const int warp_n = wid >> 1;
    const int n0 = blockIdx.y * 128;

    const uint32_t a_row = warp_m * 64 + (lane & 15);
    const uint32_t a_kb  = (uint32_t)(lane >> 4) * 16;
    const uint32_t b_row = warp_n * 32 + (lane & 7) + ((lane >> 4) & 1) * 8;
    const uint32_t b_kb  = (uint32_t)((lane >> 3) & 1) * 16;

    kd_loadB(SB, n0, tid);                              // group B
    {
        const int m0f = blockIdx.x * 8 * 128;
        kd_loadA(SA0, m0f, 0,  tid);                    // tile0 chunk0
        kd_loadA(SA1, m0f, 64, tid);                    // tile0 chunk1
    }

    for (int r = 0; r < 8; r++) {
        const int m0c = (blockIdx.x * 8 + r) * 128;
        const int m0n = (blockIdx.x * 8 + (r < 7 ? r + 1 : r)) * 128;

        float acc[4][4][4];
        #pragma unroll
        for (int i = 0; i < 4; i++)
            #pragma unroll
            for (int j = 0; j < 4; j++)
                #pragma unroll
                for (int qq = 0; qq < 4; qq++) acc[i][j][qq] = 0.f;

        // Invariant at loop head: 2 groups pending (cur chunk0 -> SA0,
        // cur chunk1 -> SA1). WAIT1 before each consume.
        CP_WAIT1();  __syncthreads();       // chunk0 (and B on r==0) ready
        kd_compute(SA0, SB, 0, a_row, a_kb, b_row, b_kb, acc);
        __syncthreads();
        kd_loadA(SA0, m0c, 128, tid);       // chunk2
        CP_WAIT1();  __syncthreads();       // chunk1 ready
        kd_compute(SA1, SB, 1, a_row, a_kb, b_row, b_kb, acc);
        __syncthreads();
        kd_loadA(SA1, m0c, 192, tid);       // chunk3
        CP_WAIT1();  __syncthreads();       // chunk2 ready
        kd_compute(SA0, SB, 2, a_row, a_kb, b_row, b_kb, acc);
        __syncthreads();
        kd_loadA(SA0, m0n, 0, tid);         // next tile chunk0
        CP_WAIT1();  __syncthreads();       // chunk3 ready
        kd_compute(SA1, SB, 3, a_row, a_kb, b_row, b_kb, acc);
        __syncthreads();
        kd_loadA(SA1, m0n, 64, tid);        // next tile chunk1

        // ---- epilogue (overlaps in-flight next-tile loads) ----
        #pragma unroll
        for (int nb = 0; nb < 4; nb++) {
            const int col = n0 + warp_n * 32 + nb * 8 + (lane & 3) * 2;
            const float2 bb = *(const float2*)&bout[col];
            #pragma unroll
            for (int mb = 0; mb < 4; mb++) {
                const int row = m0c + warp_m * 64 + mb * 16 + (lane >> 2);
                float2 v0, v1;
                v0.x = acc[mb][nb][0] + bb.x;  v0.y = acc[mb][nb][1] + bb.y;
                v1.x = acc[mb][nb][2] + bb.x;  v1.y = acc[mb][nb][3] + bb.y;
                *(float2*)&out[(size_t)row * NPAR + col]       = v0;
                *(float2*)&out[(size_t)(row + 8) * NPAR + col] = v1;
            }
        }
    }
    CP_WAIT0();   // drain trailing (duplicate) loads before exit
}

// ============================================================================
extern "C" void kernel_launch(void* const* d_in, const int* in_sizes, int n_in,
                              void* d_out, int out_size)
{
    const float* actions = (const float*)d_in[0];
    const float* obs     = (const float*)d_in[1];
    const float* Wci     = (const float*)d_in[2];
    const float* vci     = (const float*)d_in[3];
    const float* gci     = (const float*)d_in[4];
    const float* bci     = (const float*)d_in[5];
    const float* Wcl     = (const float*)d_in[6];
    const float* bcl     = (const float*)d_in[7];
    const float* Win     = (const float*)d_in[8];
    const float* vin     = (const float*)d_in[9];
    const float* gin     = (const float*)d_in[10];
    const float* bin     = (const float*)d_in[11];
    const float* Wk      = (const float*)d_in[12];
    const float* Wr      = (const float*)d_in[13];
    const float* vl      = (const float*)d_in[14];
    const float* gl      = (const float*)d_in[15];
    const float* bl      = (const float*)d_in[16];
    const float* Wd0     = (const float*)d_in[17];
    const float* vd0     = (const float*)d_in[18];
    const float* gd0     = (const float*)d_in[19];
    const float* bd0     = (const float*)d_in[20];
    const float* Wout    = (const float*)d_in[21];
    const float* bout    = (const float*)d_in[22];
    float* out = (float*)d_out;

    kWA<<<KWA_NW + 128, 256>>>(Wout, actions, obs, Wci, vci, gci, bci, Wcl, bcl,
                               Win, vin, gin, bin, Wk);
    kB<<<8, 512>>>(Wr, vl, gl, bl);
    kC<<<128, 256>>>(Wd0, vd0, gd0, bd0);

    cudaFuncSetAttribute(kD, cudaFuncAttributeMaxDynamicSharedMemorySize, KD_SMEM);
    dim3 gD(2, NPAR / 128);   // x = row halves, y = col tiles (516)
    kD<<<gD, 256, KD_SMEM>>>(bout, out);
}

// round 16
// speedup vs baseline: 2.0576x; 2.0576x over previous
#include <cuda_runtime.h>
#include <cuda_bf16.h>
#include <cstdint>

#define NB     2048
#define NPAR   66048

// Scratch (device globals; allocation is forbidden)
__device__ __align__(16) float g_G [NB * 1024];            // X@Wk precomputed gates
__device__ __align__(16) float g_H [NB * 256];             // LSTM hidden outputs
__device__ __align__(16) __nv_bfloat16 g_Ah[NB * 256];     // X3 hi (bf16 split)
__device__ __align__(16) __nv_bfloat16 g_Al[NB * 256];     // X3 lo
__device__ __align__(16) __nv_bfloat16 g_Bh[(size_t)NPAR * 256]; // W^T hi, K-major [n][k]
__device__ __align__(16) __nv_bfloat16 g_Bl[(size_t)NPAR * 256]; // W^T lo

__device__ __forceinline__ float sigf(float x) {
    return __frcp_rn(1.0f + __expf(-x));
}

__device__ __forceinline__ float2 fma2(float2 a, float2 b, float2 c) {
    unsigned long long A, Bv, C, D;
    asm("mov.b64 %0, {%1,%2};" : "=l"(A)  : "f"(a.x), "f"(a.y));
    asm("mov.b64 %0, {%1,%2};" : "=l"(Bv) : "f"(b.x), "f"(b.y));
    asm("mov.b64 %0, {%1,%2};" : "=l"(C)  : "f"(c.x), "f"(c.y));
    asm("fma.rn.f32x2 %0, %1, %2, %3;" : "=l"(D) : "l"(A), "l"(Bv), "l"(C));
    float2 r;
    asm("mov.b64 {%0,%1}, %2;" : "=f"(r.x), "=f"(r.y) : "l"(D));
    return r;
}

// mov-free packed dual FMA: all operands already u64 register pairs
__device__ __forceinline__ unsigned long long fma2u(
    unsigned long long a, unsigned long long b, unsigned long long c) {
    unsigned long long d;
    asm("fma.rn.f32x2 %0, %1, %2, %3;" : "=l"(d) : "l"(a), "l"(b), "l"(c));
    return d;
}

__device__ __forceinline__ unsigned smem_u32(const void* p) {
    unsigned a;
    asm("{ .reg .u64 t; cvta.to.shared.u64 t, %1; cvt.u32.u64 %0, t; }" : "=r"(a) : "l"(p));
    return a;
}

// ---- async-copy / HMMA helpers ---------------------------------------------
#define SWZ(x) ((x) ^ (((x) >> 3) & 0x70))

#define CP_ASYNC16(dst, src) \
    asm volatile("cp.async.cg.shared.global [%0], [%1], 16;" :: "r"(dst), "l"(src) : "memory")
#define CP_COMMIT()  asm volatile("cp.async.commit_group;" ::: "memory")
#define CP_WAIT1()   asm volatile("cp.async.wait_group 1;" ::: "memory")
#define CP_WAIT0()   asm volatile("cp.async.wait_group 0;" ::: "memory")

#define LDSM_X4(r0, r1, r2, r3, addr) \
    asm volatile("ldmatrix.sync.aligned.m8n8.x4.shared.b16 {%0,%1,%2,%3}, [%4];" \
                 : "=r"(r0), "=r"(r1), "=r"(r2), "=r"(r3) : "r"(addr))

#define MMA16816(d, a, b0, b1) \
    asm volatile("mma.sync.aligned.m16n8k16.row.col.f32.bf16.bf16.f32 " \
                 "{%0,%1,%2,%3}, {%4,%5,%6,%7}, {%8,%9}, {%0,%1,%2,%3};" \
                 : "+f"((d)[0]), "+f"((d)[1]), "+f"((d)[2]), "+f"((d)[3]) \
                 : "r"((a)[0]), "r"((a)[1]), "r"((a)[2]), "r"((a)[3]), \
                   "r"(b0), "r"(b1))

// ===== Kernel WA: fused kW (blocks 0..2063) + kA (blocks 2064..2191) ========
#define KWA_NW (NPAR / 32)   // 2064

__global__ __launch_bounds__(256) void kWA(
    const float* __restrict__ Wout,
    const float* __restrict__ actions, const float* __restrict__ obs,
    const float* __restrict__ Wci, const float* __restrict__ vci,
    const float* __restrict__ gci, const float* __restrict__ bci,
    const float* __restrict__ Wcl, const float* __restrict__ bcl,
    const float* __restrict__ Win, const float* __restrict__ vin,
    const float* __restrict__ gin, const float* __restrict__ bin,
    const float* __restrict__ Wk)
{
    __shared__ float sm1[16 * 256];
    __shared__ float sm2[16 * 256];
    const int tid = threadIdx.x;

    if (blockIdx.x < KWA_NW) {
        // ------- kW part: transpose+split a 256k x 32n block -------
        float* sm = sm1;
        const int n0 = blockIdx.x * 32;
        #pragma unroll 4
        for (int it = 0; it < 32; it++) {
            const int idx = it * 256 + tid;
            const int k = idx >> 5, j = idx & 31;
            sm[j * 256 + (k ^ j)] = Wout[(size_t)k * NPAR + n0 + j];
        }
        __syncthreads();
        const int j  = tid & 31;
        const int kq = tid >> 5;
        __nv_bfloat16* ph = g_Bh + (size_t)(n0 + j) * 256 + kq * 32;
        __nv_bfloat16* pl = g_Bl + (size_t)(n0 + j) * 256 + kq * 32;
        #pragma unroll
        for (int kk = 0; kk < 32; kk++) {
            const float w = sm[j * 256 + ((kq * 32 + kk) ^ j)];
            const __nv_bfloat16 hi = __float2bfloat16(w);
            const __nv_bfloat16 lo = __float2bfloat16(w - __bfloat162float(hi));
            ph[kk] = hi;
            pl[kk] = lo;
        }
        return;
    }

    // ------- kA part -------
    const int r0 = (blockIdx.x - KWA_NW) * 16;

    { // t1 = actions @ Wci -> sm1[16][64]
        const int j = tid & 63, rr = tid >> 6;
        #pragma unroll
        for (int q = 0; q < 4; q++) {
            const int r = rr + q * 4;
            float acc = 0.f;
            #pragma unroll
            for (int k = 0; k < 16; k++)
                acc += actions[(r0 + r) * 16 + k] * Wci[k * 64 + j];
            sm1[r * 64 + j] = acc;
        }
    }
    __syncthreads();
    { // evonorm(groups=8) -> sm2[16][64]
        const int j = tid & 63, rr = tid >> 6;
        const float v = vci[j], g = gci[j], bb = bci[j];
        #pragma unroll
        for (int q = 0; q < 4; q++) {
            const int r = rr + q * 4;
            const float* row = &sm1[r * 64 + (j & ~7)];
            float s1 = 0.f, s2 = 0.f;
            #pragma unroll
            for (int e = 0; e < 8; e++) { float t = row[e]; s1 += t; s2 += t * t; }
            const float mean = s1 * 0.125f;
            const float var  = s2 * 0.125f - mean * mean;
            const float x = sm1[r * 64 + j];
            sm2[r * 64 + j] = x * sigf(v * x) * rsqrtf(var + 1e-5f) * g + bb;
        }
    }
    __syncthreads();
    { // x = a1 @ Wcl + bcl + obs -> sm1[16][64]
        const int j = tid & 63, rr = tid >> 6;
        const float bj = bcl[j];
        float acc[4];
        #pragma unroll
        for (int q = 0; q < 4; q++)
            acc[q] = bj + obs[(r0 + rr + q * 4) * 64 + j];
        for (int k = 0; k < 64; k++) {
            const float w = Wcl[k * 64 + j];
            #pragma unroll
            for (int q = 0; q < 4; q++)
                acc[q] += sm2[(rr + q * 4) * 64 + k] * w;
        }
        #pragma unroll
        for (int q = 0; q < 4; q++)
            sm1[(rr + q * 4) * 64 + j] = acc[q];
    }
    __syncthreads();
    { // t2 = x @ Win -> sm2[16][256]
        const int j = tid;
        float acc[16];
        #pragma unroll
        for (int r = 0; r < 16; r++) acc[r] = 0.f;
        for (int k = 0; k < 64; k++) {
            const float w = Win[k * 256 + j];
            #pragma unroll
            for (int r = 0; r < 16; r++) acc[r] += sm1[r * 64 + k] * w;
        }
        #pragma unroll
        for (int r = 0; r < 16; r++) sm2[r * 256 + j] = acc[r];
    }
    __syncthreads();
    { // evonorm(group size 8) -> sm1[16][256]
        const int j = tid;
        const float v = vin[j], g = gin[j], bb = bin[j];
        for (int r = 0; r < 16; r++) {
            const float* row = &sm2[r * 256 + (j & ~7)];
            float s1 = 0.f, s2 = 0.f;
            #pragma unroll
            for (int e = 0; e < 8; e++) { float t = row[e]; s1 += t; s2 += t * t; }
            const float mean = s1 * 0.125f;
            const float var  = s2 * 0.125f - mean * mean;
            const float x = sm2[r * 256 + j];
            sm1[r * 256 + j] = x * sigf(v * x) * rsqrtf(var + 1e-5f) * g + bb;
        }
    }
    __syncthreads();
    { // G = x_in @ Wk  (thread: 4 cols x 16 rows)
        const int c0 = tid * 4;
        float2 acc[16][2];
        #pragma unroll
        for (int r = 0; r < 16; r++) { acc[r][0] = make_float2(0.f,0.f); acc[r][1] = make_float2(0.f,0.f); }
        for (int k = 0; k < 256; k++) {
            const float4 w4 = *(const float4*)&Wk[k * 1024 + c0];
            const float2 wa = make_float2(w4.x, w4.y);
            const float2 wb = make_float2(w4.z, w4.w);
            #pragma unroll
            for (int r = 0; r < 16; r++) {
                const float x = sm1[r * 256 + k];
                const float2 xx = make_float2(x, x);
                acc[r][0] = fma2(wa, xx, acc[r][0]);
                acc[r][1] = fma2(wb, xx, acc[r][1]);
            }
        }
        #pragma unroll
        for (int r = 0; r < 16; r++) {
            float4 o;
            o.x = acc[r][0].x; o.y = acc[r][0].y; o.z = acc[r][1].x; o.w = acc[r][1].y;
            *(float4*)&g_G[(size_t)(r0 + r) * 1024 + c0] = o;
        }
    }
}

// ===== Kernel B: sequential LSTM, 8-CTA cluster (R14 proven variant) ========
// Thread (g, kw): g = col-group (4 cols), kw = k-window (16 k's). Warp lanes
// share kw -> all smem h loads are pure broadcast (conflict-free).
// GEMV phase1 packed f32x2 -> s_part; phase2 pairwise tree (warps 0-3,
// bar.sync 1). Push: warp0 lanes 0-7, one release-arrive per source CTA.
__global__ void __launch_bounds__(512, 1) __cluster_dims__(8, 1, 1)
kB(const float* __restrict__ Wr, const float* __restrict__ vl_,
   const float* __restrict__ gl_, const float* __restrict__ bl_)
{
    __shared__ __align__(16) float s_hb[2][256];        // h buffers (remote-written)
    __shared__ __align__(16) float s_part[2][16 * 128]; // GEMV partials, 2x8KB
    __shared__ __align__(16) float s_z[128];
    __shared__ __align__(16) float s_hout[32];
    __shared__ __align__(8)  unsigned long long s_mbar[2];

    const int tid = threadIdx.x;
    unsigned rank;
    asm("mov.u32 %0, %%cluster_ctarank;" : "=r"(rank));

    const int g   = tid & 31;        // col-group: cols [g*4, g*4+4)
    const int kw  = tid >> 5;        // k-window:  k    [kw*16, kw*16+16)
    const int gg  = g >> 3;          // gate 0..3
    const int cc0 = (g & 7) * 4;     // channel base within this CTA's 32
    const int gcol0 = gg * 256 + (int)rank * 32 + cc0;   // global col of c=0
    const int k0    = kw * 16;

    // register-resident weights, packed as (k, k+1) pairs per column: u64
    unsigned long long wv[4][8];
    #pragma unroll
    for (int p = 0; p < 8; p++) {
        #pragma unroll
        for (int c = 0; c < 4; c++) {
            const float w0 = Wr[(size_t)(k0 + 2*p)     * 1024 + gcol0 + c];
            const float w1 = Wr[(size_t)(k0 + 2*p + 1) * 1024 + gcol0 + c];
            asm("mov.b64 %0, {%1,%2};" : "=l"(wv[c][p]) : "f"(w0), "f"(w1));
        }
    }

    // cell params for warp 0 (channel ch = rank*32 + lane)
    float vl = 0.f, gl = 0.f, bl = 0.f, cst = 0.f;
    if (tid < 32) {
        const int ch = (int)rank * 32 + tid;
        vl = vl_[ch]; gl = gl_[ch]; bl = bl_[ch];
    }

    // push addresses for warp0 lanes 0-7 (lane = dest CTA)
    unsigned r_h0 = 0, r_h1 = 0, r_b0 = 0, r_b1 = 0;
    if (tid < 8) {
        const unsigned d = (unsigned)tid;
        unsigned lh0 = smem_u32(&s_hb[0][rank * 32]);
        unsigned lh1 = smem_u32(&s_hb[1][rank * 32]);
        unsigned lb0 = smem_u32(&s_mbar[0]);
        unsigned lb1 = smem_u32(&s_mbar[1]);
        asm("mapa.shared::cluster.u32 %0, %1, %2;" : "=r"(r_h0) : "r"(lh0), "r"(d));
        asm("mapa.shared::cluster.u32 %0, %1, %2;" : "=r"(r_h1) : "r"(lh1), "r"(d));
        asm("mapa.shared::cluster.u32 %0, %1, %2;" : "=r"(r_b0) : "r"(lb0), "r"(d));
        asm("mapa.shared::cluster.u32 %0, %1, %2;" : "=r"(r_b1) : "r"(lb1), "r"(d));
    }

    if (tid == 0) {
        asm volatile("mbarrier.init.shared.b64 [%0], %1;" :: "r"(smem_u32(&s_mbar[0])), "r"(8u) : "memory");
        asm volatile("mbarrier.init.shared.b64 [%0], %1;" :: "r"(smem_u32(&s_mbar[1])), "r"(8u) : "memory");
    }
    if (tid < 256) { s_hb[0][tid] = 0.f; s_hb[1][tid] = 0.f; }
    __syncthreads();
    asm volatile("barrier.cluster.arrive.aligned;" ::: "memory");
    asm volatile("barrier.cluster.wait.aligned;"   ::: "memory");

    // initial push: zeros (h_{-1}) into buffer 1
    if (tid < 8) {
        #pragma unroll
        for (int i = 0; i < 8; i++)
            asm volatile("st.shared::cluster.v4.f32 [%0], {%1,%1,%1,%1};"
                         :: "r"(r_h1 + i * 16), "f"(0.f) : "memory");
        asm volatile("mbarrier.arrive.release.cluster.shared::cluster.b64 _, [%0];"
                     :: "r"(r_b1) : "memory");
    }

    unsigned par0 = 0u, par1 = 0u;

    // prefetch gate term for step 0 (phase-2 threads)
    const int gcol2 = (tid >> 5) * 256 + (int)rank * 32 + (tid & 31);
    float gt = (tid < 128) ? g_G[gcol2] : 0.f;

    for (int t = 0; t < NB; t++) {
        const int rb = (t + 1) & 1;      // buffer holding h_{t-1}
        const int wb = t & 1;            // buffer receiving h_t
        const int pp = t & 1;            // s_part parity

        { // wait for all 8 source-CTA pushes of h_{t-1}
            const unsigned a = smem_u32(&s_mbar[rb]);
            const unsigned ph = rb ? par1 : par0;
            unsigned done;
            asm volatile(
                "{\n\t.reg .pred p;\n\t"
                "mbarrier.try_wait.parity.acquire.cluster.shared::cta.b64 p, [%1], %2;\n\t"
                "selp.b32 %0, 1, 0, p;\n\t}"
                : "=r"(done) : "r"(a), "r"(ph) : "memory");
            if (!done) {
                asm volatile(
                    "{\n\t.reg .pred P1;\n\t"
                    "WLB_%=:\n\t"
                    "mbarrier.try_wait.parity.acquire.cluster.shared::cta.b64 P1, [%0], %1, 0x989680;\n\t"
                    "@P1 bra.uni WDB_%=;\n\t"
                    "bra.uni WLB_%=;\n\t"
                    "WDB_%=:\n\t}"
                    :: "r"(a), "r"(ph) : "memory");
            }
            if (rb) par1 ^= 1u; else par0 ^= 1u;
        }

        // ---- GEMV phase 1: 4 cols x 16 k per thread, packed f32x2 ----
        {
            const unsigned long long* hp =
                (const unsigned long long*)&s_hb[rb][k0];
            unsigned long long a0 = 0ULL, a1 = 0ULL, a2 = 0ULL, a3 = 0ULL;
            #pragma unroll
            for (int p = 0; p < 8; p++) {
                const unsigned long long h2 = hp[p];
                a0 = fma2u(wv[0][p], h2, a0);
                a1 = fma2u(wv[1][p], h2, a1);
                a2 = fma2u(wv[2][p], h2, a2);
                a3 = fma2u(wv[3][p], h2, a3);
            }
            float2 f0, f1, f2, f3;
            asm("mov.b64 {%0,%1}, %2;" : "=f"(f0.x), "=f"(f0.y) : "l"(a0));
            asm("mov.b64 {%0,%1}, %2;" : "=f"(f1.x), "=f"(f1.y) : "l"(a1));
            asm("mov.b64 {%0,%1}, %2;" : "=f"(f2.x), "=f"(f2.y) : "l"(a2));
            asm("mov.b64 {%0,%1}, %2;" : "=f"(f3.x), "=f"(f3.y) : "l"(a3));
            float4 p4;
            p4.x = f0.x + f0.y; p4.y = f1.x + f1.y;
            p4.z = f2.x + f2.y; p4.w = f3.x + f3.y;
            *(float4*)&s_part[pp][kw * 128 + g * 4] = p4;
        }
        __syncthreads();   // all 512: partials of step t visible

        // ---- phase2 + cell: warps 0-3 only; warps 4-15 go to next wait ----
        if (tid < 128) {
            float v[16];
            #pragma unroll
            for (int k2 = 0; k2 < 16; k2++)
                v[k2] = s_part[pp][k2 * 128 + tid];
            const float s =
                (((v[0] + v[1]) + (v[2] + v[3])) + ((v[4] + v[5]) + (v[6] + v[7]))) +
                (((v[8] + v[9]) + (v[10] + v[11])) + ((v[12] + v[13]) + (v[14] + v[15]))) + gt;
            s_z[tid] = s;
            if (t + 1 < NB) gt = g_G[(size_t)(t + 1) * 1024 + gcol2];

            asm volatile("bar.sync 1, 128;" ::: "memory");

            if (tid < 32) {
                const float zi = s_z[tid];
                const float zf = s_z[32 + tid];
                const float zc = s_z[64 + tid];
                const float zo = s_z[96 + tid];

                float s1 = zc, s2 = zc * zc;
                s1 += __shfl_xor_sync(0xffffffffu, s1, 1);  s2 += __shfl_xor_sync(0xffffffffu, s2, 1);
                s1 += __shfl_xor_sync(0xffffffffu, s1, 2);  s2 += __shfl_xor_sync(0xffffffffu, s2, 2);
                s1 += __shfl_xor_sync(0xffffffffu, s1, 4);  s2 += __shfl_xor_sync(0xffffffffu, s2, 4);
                float mean = s1 * 0.125f;
                float var  = s2 * 0.125f - mean * mean;
                const float ecc = zc * sigf(vl * zc) * rsqrtf(var + 1e-5f) * gl + bl;

                cst = sigf(zf) * cst + sigf(zi) * ecc;

                s1 = cst; s2 = cst * cst;
                s1 += __shfl_xor_sync(0xffffffffu, s1, 1);  s2 += __shfl_xor_sync(0xffffffffu, s2, 1);
                s1 += __shfl_xor_sync(0xffffffffu, s1, 2);  s2 += __shfl_xor_sync(0xffffffffu, s2, 2);
                s1 += __shfl_xor_sync(0xffffffffu, s1, 4);  s2 += __shfl_xor_sync(0xffffffffu, s2, 4);
                mean = s1 * 0.125f;
                var  = s2 * 0.125f - mean * mean;
                const float ecn = cst * sigf(vl * cst) * rsqrtf(var + 1e-5f) * gl + bl;

                const float h = sigf(zo) * ecn;
                s_hout[tid] = h;
                __syncwarp();

                // push h_t: lane d -> dest CTA d (8 x st.v4 + 1 release-arrive)
                if (tid < 8) {
                    const unsigned rh  = wb ? r_h1 : r_h0;
                    const unsigned rbb = wb ? r_b1 : r_b0;
                    #pragma unroll
                    for (int i = 0; i < 8; i++) {
                        const float4 hv4 = *(const float4*)&s_hout[i * 4];
                        asm volatile("st.shared::cluster.v4.f32 [%0], {%1,%2,%3,%4};"
                                     :: "r"(rh + i * 16), "f"(hv4.x), "f"(hv4.y), "f"(hv4.z), "f"(hv4.w)
                                     : "memory");
                    }
                    asm volatile("mbarrier.arrive.release.cluster.shared::cluster.b64 _, [%0];"
                                 :: "r"(rbb) : "memory");
                }
                g_H[(size_t)t * 256 + rank * 32 + tid] = h;
            }
        }
    }

    asm volatile("barrier.cluster.arrive.aligned;" ::: "memory");
    asm volatile("barrier.cluster.wait.aligned;"   ::: "memory");
}

// ===== Kernel C: dense_0 + evonorm -> bf16 hi/lo split (g_Ah/g_Al) ==========
__global__ __launch_bounds__(256) void kC(
    const float* __restrict__ Wd0, const float* __restrict__ vd,
    const float* __restrict__ gd,  const float* __restrict__ bd)
{
    __shared__ float sm1[16 * 256];
    __shared__ float sm2[16 * 256];
    const int tid = threadIdx.x;
    const int r0  = blockIdx.x * 16;

    const float4* src = (const float4*)(g_H + (size_t)r0 * 256);
    for (int i = tid; i < 1024; i += 256)
        ((float4*)sm1)[i] = src[i];
    __syncthreads();

    const int j = tid;
    float acc[16];
    #pragma unroll
    for (int r = 0; r < 16; r++) acc[r] = 0.f;
    for (int k4 = 0; k4 < 64; k4++) {
        const int k = k4 * 4;
        const float w0 = Wd0[(k+0)*256 + j];
        const float w1 = Wd0[(k+1)*256 + j];
        const float w2 = Wd0[(k+2)*256 + j];
        const float w3 = Wd0[(k+3)*256 + j];
        #pragma unroll
        for (int r = 0; r < 16; r++) {
            const float4 x = *(const float4*)&sm1[r * 256 + k];
            acc[r] += x.x*w0 + x.y*w1 + x.z*w2 + x.w*w3;
        }
    }
    #pragma unroll
    for (int r = 0; r < 16; r++) sm2[r * 256 + j] = acc[r];
    __syncthreads();

    const float v = vd[j], g = gd[j], bb = bd[j];
    for (int r = 0; r < 16; r++) {
        const float* row = &sm2[r * 256 + (j & ~7)];
        float s1 = 0.f, s2 = 0.f;
        #pragma unroll
        for (int e = 0; e < 8; e++) { float t = row[e]; s1 += t; s2 += t * t; }
        const float mean = s1 * 0.125f;
        const float var  = s2 * 0.125f - mean * mean;
        const float x = sm2[r * 256 + j];
        const float y = x * sigf(v * x) * rsqrtf(var + 1e-5f) * g + bb;
        const __nv_bfloat16 hi = __float2bfloat16(y);
        const __nv_bfloat16 lo = __float2bfloat16(y - __bfloat162float(hi));
        g_Ah[(size_t)(r0 + r) * 256 + j] = hi;
        g_Al[(size_t)(r0 + r) * 256 + j] = lo;
    }
}

// ===== Kernel D: HMMA bf16 3-split GEMM, B smem-resident, A streamed ========
// CTA owns a 128-col B slice (all K, 128KB smem); 8 row tiles, A chunks
// double-buffered and software-pipelined ACROSS tiles (epilogue overlaps
// the next tile's A loads). Grid: x = 2 row halves, y = 516 col tiles.
#define KDB_SZ    131072
#define KDA_STAGE 32768
#define KD_SMEM   (KDB_SZ + 2 * KDA_STAGE)   // 196608

__device__ __forceinline__ void kd_loadB(uint32_t SB, int n0, int tid)
{
    #pragma unroll
    for (int c = 0; c < 4; c++) {
        #pragma unroll
        for (int sp = 0; sp < 2; sp++) {
            const __nv_bfloat16* gB = sp ? g_Bl : g_Bh;
            const uint32_t db = SB + c * 32768u + sp * 16384u;
            #pragma unroll
            for (int i = 0; i < 4; i++) {
                const int g2 = tid + i * 256;
                const int row = g2 >> 3, j = g2 & 7;
                CP_ASYNC16(db + SWZ(row * 128 + j * 16),
                           gB + (size_t)(n0 + row) * 256 + c * 64 + j * 8);
            }
        }
    }
    CP_COMMIT();
}

__device__ __forceinline__ void kd_loadA(uint32_t stage, int m0, int koff, int tid)
{
    #pragma unroll
    for (int sp = 0; sp < 2; sp++) {
        const __nv_bfloat16* gA = sp ? g_Al : g_Ah;
        const uint32_t db = stage + sp * 16384u;
        #pragma unroll
        for (int i = 0; i < 4; i++) {
            const int g2 = tid + i * 256;
            const int row = g2 >> 3, j = g2 & 7;
            CP_ASYNC16(db + SWZ(row * 128 + j * 16),
                       gA + (size_t)(m0 + row) * 256 + koff + j * 8);
        }
    }
    CP_COMMIT();
}

__device__ __forceinline__ void kd_compute(uint32_t Astage, uint32_t SB, int blk,
                                           uint32_t a_row, uint32_t a_kb,
                                           uint32_t b_row, uint32_t b_kb,
                                           float acc[4][4][4])
{
    #pragma unroll
    for (int split = 0; split < 3; split++) {
        const uint32_t Abase = Astage + (split == 2 ? 16384u : 0u);
        const uint32_t Bbase = SB + blk * 32768u + (split == 1 ? 16384u : 0u);
        #pragma unroll
        for (int ks = 0; ks < 4; ks++) {
            const uint32_t kk2 = (uint32_t)ks * 32;
            uint32_t af[4][4];
            #pragma unroll
            for (int mb = 0; mb < 4; mb++) {
                const uint32_t addr = Abase + SWZ((a_row + mb * 16) * 128 + kk2 + a_kb);
                LDSM_X4(af[mb][0], af[mb][1], af[mb][2], af[mb][3], addr);
            }
            uint32_t bfr[2][4];
            #pragma unroll
            for (int nb2 = 0; nb2 < 2; nb2++) {
                const uint32_t addr = Bbase + SWZ((b_row + nb2 * 16) * 128 + kk2 + b_kb);
                LDSM_X4(bfr[nb2][0], bfr[nb2][1], bfr[nb2][2], bfr[nb2][3], addr);
            }
            #pragma unroll
            for (int mb = 0; mb < 4; mb++) {
                MMA16816(acc[mb][0], af[mb], bfr[0][0], bfr[0][1]);
                MMA16816(acc[mb][1], af[mb], bfr[0][2], bfr[0][3]);
                MMA16816(acc[mb][2], af[mb], bfr[1][0], bfr[1][1]);
                MMA16816(acc[mb][3], af[mb], bfr[1][2], bfr[1][3]);
            }
        }
    }
}

__global__ void __launch_bounds__(256)
kD(const float* __restrict__ bout, float* __restrict__ out)
{
    extern __shared__ __align__(1024) char smem[];
    const uint32_t SB  = smem_u32(smem);
    const uint32_t SA0 = SB + KDB_SZ;
    const uint32_t SA1 = SA0 + KDA_STAGE;
    const int tid = threadIdx.x;
    const int wid = tid >> 5, lane = tid & 31;
    const int warp_m = wid & 1;
    const int warp_n = wid >> 1;
    const int n0 = blockIdx.y * 128;

    const uint32_t a_row = warp_m * 64 + (lane & 15);
    const uint32_t a_kb  = (uint32_t)(lane >> 4) * 16;
    const uint32_t b_row = warp_n * 32 + (lane & 7) + ((lane >> 4) & 1) * 8;
    const uint32_t b_kb  = (uint32_t)((lane >> 3) & 1) * 16;

    kd_loadB(SB, n0, tid);                              // group B
    {
        const int m0f = blockIdx.x * 8 * 128;
        kd_loadA(SA0, m0f, 0,  tid);                    // tile0 chunk0
        kd_loadA(SA1, m0f, 64, tid);                    // tile0 chunk1
    }

    for (int r = 0; r < 8; r++) {
        const int m0c = (blockIdx.x * 8 + r) * 128;
        const int m0n = (blockIdx.x * 8 + (r < 7 ? r + 1 : r)) * 128;

        float acc[4][4][4];
        #pragma unroll
        for (int i = 0; i < 4; i++)
            #pragma unroll
            for (int j = 0; j < 4; j++)
                #pragma unroll
                for (int qq = 0; qq < 4; qq++) acc[i][j][qq] = 0.f;

        // Invariant at loop head: 2 groups pending (cur chunk0 -> SA0,
        // cur chunk1 -> SA1). WAIT1 before each consume.
        CP_WAIT1();  __syncthreads();       // chunk0 (and B on r==0) ready
        kd_compute(SA0, SB, 0, a_row, a_kb, b_row, b_kb, acc);
        __syncthreads();
        kd_loadA(SA0, m0c, 128, tid);       // chunk2
        CP_WAIT1();  __syncthreads();       // chunk1 ready
        kd_compute(SA1, SB, 1, a_row, a_kb, b_row, b_kb, acc);
        __syncthreads();
        kd_loadA(SA1, m0c, 192, tid);       // chunk3
        CP_WAIT1();  __syncthreads();       // chunk2 ready
        kd_compute(SA0, SB, 2, a_row, a_kb, b_row, b_kb, acc);
        __syncthreads();
        kd_loadA(SA0, m0n, 0, tid);         // next tile chunk0
        CP_WAIT1();  __syncthreads();       // chunk3 ready
        kd_compute(SA1, SB, 3, a_row, a_kb, b_row, b_kb, acc);
        __syncthreads();
        kd_loadA(SA1, m0n, 64, tid);        // next tile chunk1

        // ---- epilogue (overlaps in-flight next-tile loads) ----
        #pragma unroll
        for (int nb = 0; nb < 4; nb++) {
            const int col = n0 + warp_n * 32 + nb * 8 + (lane & 3) * 2;
            const float2 bb = *(const float2*)&bout[col];
            #pragma unroll
            for (int mb = 0; mb < 4; mb++) {
                const int row = m0c + warp_m * 64 + mb * 16 + (lane >> 2);
                float2 v0, v1;
                v0.x = acc[mb][nb][0] + bb.x;  v0.y = acc[mb][nb][1] + bb.y;
                v1.x = acc[mb][nb][2] + bb.x;  v1.y = acc[mb][nb][3] + bb.y;
                *(float2*)&out[(size_t)row * NPAR + col]       = v0;
                *(float2*)&out[(size_t)(row + 8) * NPAR + col] = v1;
            }
        }
    }
    CP_WAIT0();   // drain trailing (duplicate) loads before exit
}

// ============================================================================
extern "C" void kernel_launch(void* const* d_in, const int* in_sizes, int n_in,
                              void* d_out, int out_size)
{
    const float* actions = (const float*)d_in[0];
    const float* obs     = (const float*)d_in[1];
    const float* Wci     = (const float*)d_in[2];
    const float* vci     = (const float*)d_in[3];
    const float* gci     = (const float*)d_in[4];
    const float* bci     = (const float*)d_in[5];
    const float* Wcl     = (const float*)d_in[6];
    const float* bcl     = (const float*)d_in[7];
    const float* Win     = (const float*)d_in[8];
    const float* vin     = (const float*)d_in[9];
    const float* gin     = (const float*)d_in[10];
    const float* bin     = (const float*)d_in[11];
    const float* Wk      = (const float*)d_in[12];
    const float* Wr      = (const float*)d_in[13];
    const float* vl      = (const float*)d_in[14];
    const float* gl      = (const float*)d_in[15];
    const float* bl      = (const float*)d_in[16];
    const float* Wd0     = (const float*)d_in[17];
    const float* vd0     = (const float*)d_in[18];
    const float* gd0     = (const float*)d_in[19];
    const float* bd0     = (const float*)d_in[20];
    const float* Wout    = (const float*)d_in[21];
    const float* bout    = (const float*)d_in[22];
    float* out = (float*)d_out;

    kWA<<<KWA_NW + 128, 256>>>(Wout, actions, obs, Wci, vci, gci, bci, Wcl, bcl,
                               Win, vin, gin, bin, Wk);
    kB<<<8, 512>>>(Wr, vl, gl, bl);
    kC<<<128, 256>>>(Wd0, vd0, gd0, bd0);

    cudaFuncSetAttribute(kD, cudaFuncAttributeMaxDynamicSharedMemorySize, KD_SMEM);
    dim3 gD(2, NPAR / 128);   // x = row halves, y = col tiles (516)
    kD<<<gD, 256, KD_SMEM>>>(bout, out);
}

// round 17
// speedup vs baseline: 2.1407x; 1.0404x over previous
#include <cuda_runtime.h>
#include <cuda_bf16.h>
#include <cstdint>

#define NB     2048
#define NPAR   66048

// Scratch (device globals; allocation is forbidden)
__device__ __align__(16) float g_G [NB * 1024];            // X@Wk precomputed gates
__device__ __align__(16) float g_H [NB * 256];             // LSTM hidden outputs
__device__ __align__(16) __nv_bfloat16 g_Ah[NB * 256];     // X3 hi (bf16 split)
__device__ __align__(16) __nv_bfloat16 g_Al[NB * 256];     // X3 lo
__device__ __align__(16) __nv_bfloat16 g_Bh[(size_t)NPAR * 256]; // W^T hi, K-major [n][k]
__device__ __align__(16) __nv_bfloat16 g_Bl[(size_t)NPAR * 256]; // W^T lo

__device__ __forceinline__ float sigf(float x) {
    return __frcp_rn(1.0f + __expf(-x));
}

__device__ __forceinline__ float2 fma2(float2 a, float2 b, float2 c) {
    unsigned long long A, Bv, C, D;
    asm("mov.b64 %0, {%1,%2};" : "=l"(A)  : "f"(a.x), "f"(a.y));
    asm("mov.b64 %0, {%1,%2};" : "=l"(Bv) : "f"(b.x), "f"(b.y));
    asm("mov.b64 %0, {%1,%2};" : "=l"(C)  : "f"(c.x), "f"(c.y));
    asm("fma.rn.f32x2 %0, %1, %2, %3;" : "=l"(D) : "l"(A), "l"(Bv), "l"(C));
    float2 r;
    asm("mov.b64 {%0,%1}, %2;" : "=f"(r.x), "=f"(r.y) : "l"(D));
    return r;
}

// mov-free packed dual FMA: all operands already u64 register pairs
__device__ __forceinline__ unsigned long long fma2u(
    unsigned long long a, unsigned long long b, unsigned long long c) {
    unsigned long long d;
    asm("fma.rn.f32x2 %0, %1, %2, %3;" : "=l"(d) : "l"(a), "l"(b), "l"(c));
    return d;
}

__device__ __forceinline__ unsigned smem_u32(const void* p) {
    unsigned a;
    asm("{ .reg .u64 t; cvta.to.shared.u64 t, %1; cvt.u32.u64 %0, t; }" : "=r"(a) : "l"(p));
    return a;
}

// ---- async-copy / HMMA helpers ---------------------------------------------
#define SWZ(x) ((x) ^ (((x) >> 3) & 0x70))

#define CP_ASYNC16(dst, src) \
    asm volatile("cp.async.cg.shared.global [%0], [%1], 16;" :: "r"(dst), "l"(src) : "memory")
#define CP_COMMIT()  asm volatile("cp.async.commit_group;" ::: "memory")
#define CP_WAIT1()   asm volatile("cp.async.wait_group 1;" ::: "memory")
#define CP_WAIT0()   asm volatile("cp.async.wait_group 0;" ::: "memory")

#define LDSM_X4(r0, r1, r2, r3, addr) \
    asm volatile("ldmatrix.sync.aligned.m8n8.x4.shared.b16 {%0,%1,%2,%3}, [%4];" \
                 : "=r"(r0), "=r"(r1), "=r"(r2), "=r"(r3) : "r"(addr))

#define MMA16816(d, a, b0, b1) \
    asm volatile("mma.sync.aligned.m16n8k16.row.col.f32.bf16.bf16.f32 " \
                 "{%0,%1,%2,%3}, {%4,%5,%6,%7}, {%8,%9}, {%0,%1,%2,%3};" \
                 : "+f"((d)[0]), "+f"((d)[1]), "+f"((d)[2]), "+f"((d)[3]) \
                 : "r"((a)[0]), "r"((a)[1]), "r"((a)[2]), "r"((a)[3]), \
                   "r"(b0), "r"(b1))

// ===== Kernel WA: fused kW (blocks 0..2063) + kA (blocks 2064..2191) ========
#define KWA_NW (NPAR / 32)   // 2064

__global__ __launch_bounds__(256) void kWA(
    const float* __restrict__ Wout,
    const float* __restrict__ actions, const float* __restrict__ obs,
    const float* __restrict__ Wci, const float* __restrict__ vci,
    const float* __restrict__ gci, const float* __restrict__ bci,
    const float* __restrict__ Wcl, const float* __restrict__ bcl,
    const float* __restrict__ Win, const float* __restrict__ vin,
    const float* __restrict__ gin, const float* __restrict__ bin,
    const float* __restrict__ Wk)
{
    __shared__ float sm1[16 * 256];
    __shared__ float sm2[16 * 256];
    const int tid = threadIdx.x;

    if (blockIdx.x < KWA_NW) {
        // ------- kW part: transpose+split a 256k x 32n block -------
        float* sm = sm1;
        const int n0 = blockIdx.x * 32;
        #pragma unroll 4
        for (int it = 0; it < 32; it++) {
            const int idx = it * 256 + tid;
            const int k = idx >> 5, j = idx & 31;
            sm[j * 256 + (k ^ j)] = Wout[(size_t)k * NPAR + n0 + j];
        }
        __syncthreads();
        const int j  = tid & 31;
        const int kq = tid >> 5;
        __nv_bfloat16* ph = g_Bh + (size_t)(n0 + j) * 256 + kq * 32;
        __nv_bfloat16* pl = g_Bl + (size_t)(n0 + j) * 256 + kq * 32;
        #pragma unroll
        for (int kk = 0; kk < 32; kk++) {
            const float w = sm[j * 256 + ((kq * 32 + kk) ^ j)];
            const __nv_bfloat16 hi = __float2bfloat16(w);
            const __nv_bfloat16 lo = __float2bfloat16(w - __bfloat162float(hi));
            ph[kk] = hi;
            pl[kk] = lo;
        }
        return;
    }

    // ------- kA part -------
    const int r0 = (blockIdx.x - KWA_NW) * 16;

    { // t1 = actions @ Wci -> sm1[16][64]
        const int j = tid & 63, rr = tid >> 6;
        #pragma unroll
        for (int q = 0; q < 4; q++) {
            const int r = rr + q * 4;
            float acc = 0.f;
            #pragma unroll
            for (int k = 0; k < 16; k++)
                acc += actions[(r0 + r) * 16 + k] * Wci[k * 64 + j];
            sm1[r * 64 + j] = acc;
        }
    }
    __syncthreads();
    { // evonorm(groups=8) -> sm2[16][64]
        const int j = tid & 63, rr = tid >> 6;
        const float v = vci[j], g = gci[j], bb = bci[j];
        #pragma unroll
        for (int q = 0; q < 4; q++) {
            const int r = rr + q * 4;
            const float* row = &sm1[r * 64 + (j & ~7)];
            float s1 = 0.f, s2 = 0.f;
            #pragma unroll
            for (int e = 0; e < 8; e++) { float t = row[e]; s1 += t; s2 += t * t; }
            const float mean = s1 * 0.125f;
            const float var  = s2 * 0.125f - mean * mean;
            const float x = sm1[r * 64 + j];
            sm2[r * 64 + j] = x * sigf(v * x) * rsqrtf(var + 1e-5f) * g + bb;
        }
    }
    __syncthreads();
    { // x = a1 @ Wcl + bcl + obs -> sm1[16][64]
        const int j = tid & 63, rr = tid >> 6;
        const float bj = bcl[j];
        float acc[4];
        #pragma unroll
        for (int q = 0; q < 4; q++)
            acc[q] = bj + obs[(r0 + rr + q * 4) * 64 + j];
        for (int k = 0; k < 64; k++) {
            const float w = Wcl[k * 64 + j];
            #pragma unroll
            for (int q = 0; q < 4; q++)
                acc[q] += sm2[(rr + q * 4) * 64 + k] * w;
        }
        #pragma unroll
        for (int q = 0; q < 4; q++)
            sm1[(rr + q * 4) * 64 + j] = acc[q];
    }
    __syncthreads();
    { // t2 = x @ Win -> sm2[16][256]
        const int j = tid;
        float acc[16];
        #pragma unroll
        for (int r = 0; r < 16; r++) acc[r] = 0.f;
        for (int k = 0; k < 64; k++) {
            const float w = Win[k * 256 + j];
            #pragma unroll
            for (int r = 0; r < 16; r++) acc[r] += sm1[r * 64 + k] * w;
        }
        #pragma unroll
        for (int r = 0; r < 16; r++) sm2[r * 256 + j] = acc[r];
    }
    __syncthreads();
    { // evonorm(group size 8) -> sm1[16][256]
        const int j = tid;
        const float v = vin[j], g = gin[j], bb = bin[j];
        for (int r = 0; r < 16; r++) {
            const float* row = &sm2[r * 256 + (j & ~7)];
            float s1 = 0.f, s2 = 0.f;
            #pragma unroll
            for (int e = 0; e < 8; e++) { float t = row[e]; s1 += t; s2 += t * t; }
            const float mean = s1 * 0.125f;
            const float var  = s2 * 0.125f - mean * mean;
            const float x = sm2[r * 256 + j];
            sm1[r * 256 + j] = x * sigf(v * x) * rsqrtf(var + 1e-5f) * g + bb;
        }
    }
    __syncthreads();
    { // G = x_in @ Wk  (thread: 4 cols x 16 rows)
        const int c0 = tid * 4;
        float2 acc[16][2];
        #pragma unroll
        for (int r = 0; r < 16; r++) { acc[r][0] = make_float2(0.f,0.f); acc[r][1] = make_float2(0.f,0.f); }
        for (int k = 0; k < 256; k++) {
            const float4 w4 = *(const float4*)&Wk[k * 1024 + c0];
            const float2 wa = make_float2(w4.x, w4.y);
            const float2 wb = make_float2(w4.z, w4.w);
            #pragma unroll
            for (int r = 0; r < 16; r++) {
                const float x = sm1[r * 256 + k];
                const float2 xx = make_float2(x, x);
                acc[r][0] = fma2(wa, xx, acc[r][0]);
                acc[r][1] = fma2(wb, xx, acc[r][1]);
            }
        }
        #pragma unroll
        for (int r = 0; r < 16; r++) {
            float4 o;
            o.x = acc[r][0].x; o.y = acc[r][0].y; o.z = acc[r][1].x; o.w = acc[r][1].y;
            *(float4*)&g_G[(size_t)(r0 + r) * 1024 + c0] = o;
        }
    }
}

// ===== Kernel B: sequential LSTM, 8-CTA cluster, per-source mbarriers =======
// Thread (g, kw): g = col-group (4 cols), kw = k-window (16 k's). Warp lanes
// share kw -> all smem h loads are pure broadcast (conflict-free).
// Each thread's k-window lies in ONE source CTA's block (src = kw>>1), so it
// waits only on that source's 1-arrival mbarrier -> skew absorbed by GEMV.
__global__ void __launch_bounds__(512, 1) __cluster_dims__(8, 1, 1)
kB(const float* __restrict__ Wr, const float* __restrict__ vl_,
   const float* __restrict__ gl_, const float* __restrict__ bl_)
{
    __shared__ __align__(16) float s_hb[2][256];        // h buffers (remote-written)
    __shared__ __align__(16) float s_part[2][16 * 128]; // GEMV partials, 2x8KB
    __shared__ __align__(16) float s_z[128];
    __shared__ __align__(16) float s_hout[32];
    __shared__ __align__(8)  unsigned long long s_mbar[2][8];  // [parity][source]

    const int tid = threadIdx.x;
    unsigned rank;
    asm("mov.u32 %0, %%cluster_ctarank;" : "=r"(rank));

    const int g   = tid & 31;        // col-group: cols [g*4, g*4+4)
    const int kw  = tid >> 5;        // k-window:  k    [kw*16, kw*16+16)
    const int src = kw >> 1;         // source CTA owning this k-window
    const int gg  = g >> 3;          // gate 0..3
    const int cc0 = (g & 7) * 4;     // channel base within this CTA's 32
    const int gcol0 = gg * 256 + (int)rank * 32 + cc0;   // global col of c=0
    const int k0    = kw * 16;

    // register-resident weights, packed as (k, k+1) pairs per column: u64
    unsigned long long wv[4][8];
    #pragma unroll
    for (int p = 0; p < 8; p++) {
        #pragma unroll
        for (int c = 0; c < 4; c++) {
            const float w0 = Wr[(size_t)(k0 + 2*p)     * 1024 + gcol0 + c];
            const float w1 = Wr[(size_t)(k0 + 2*p + 1) * 1024 + gcol0 + c];
            asm("mov.b64 %0, {%1,%2};" : "=l"(wv[c][p]) : "f"(w0), "f"(w1));
        }
    }

    // cell params for warp 0 (channel ch = rank*32 + lane)
    float vl = 0.f, gl = 0.f, bl = 0.f, cst = 0.f;
    if (tid < 32) {
        const int ch = (int)rank * 32 + tid;
        vl = vl_[ch]; gl = gl_[ch]; bl = bl_[ch];
    }

    // my local wait addresses (per parity, fixed source)
    const unsigned w_b0 = smem_u32(&s_mbar[0][src]);
    const unsigned w_b1 = smem_u32(&s_mbar[1][src]);

    // push addresses for warp0 lanes 0-7 (lane = dest CTA); arrive on the
    // dest's slot for THIS rank: &s_mbar[parity][rank]
    unsigned r_h0 = 0, r_h1 = 0, r_b0 = 0, r_b1 = 0;
    if (tid < 8) {
        const unsigned d = (unsigned)tid;
        unsigned lh0 = smem_u32(&s_hb[0][rank * 32]);
        unsigned lh1 = smem_u32(&s_hb[1][rank * 32]);
        unsigned lb0 = smem_u32(&s_mbar[0][rank]);
        unsigned lb1 = smem_u32(&s_mbar[1][rank]);
        asm("mapa.shared::cluster.u32 %0, %1, %2;" : "=r"(r_h0) : "r"(lh0), "r"(d));
        asm("mapa.shared::cluster.u32 %0, %1, %2;" : "=r"(r_h1) : "r"(lh1), "r"(d));
        asm("mapa.shared::cluster.u32 %0, %1, %2;" : "=r"(r_b0) : "r"(lb0), "r"(d));
        asm("mapa.shared::cluster.u32 %0, %1, %2;" : "=r"(r_b1) : "r"(lb1), "r"(d));
    }

    if (tid < 16) {
        asm volatile("mbarrier.init.shared.b64 [%0], %1;"
                     :: "r"(smem_u32(&s_mbar[tid >> 3][tid & 7])), "r"(1u) : "memory");
    }
    if (tid < 256) { s_hb[0][tid] = 0.f; s_hb[1][tid] = 0.f; }
    __syncthreads();
    asm volatile("barrier.cluster.arrive.aligned;" ::: "memory");
    asm volatile("barrier.cluster.wait.aligned;"   ::: "memory");

    // initial push: zeros (h_{-1}) into buffer 1
    if (tid < 8) {
        #pragma unroll
        for (int i = 0; i < 8; i++)
            asm volatile("st.shared::cluster.v4.f32 [%0], {%1,%1,%1,%1};"
                         :: "r"(r_h1 + i * 16), "f"(0.f) : "memory");
        asm volatile("mbarrier.arrive.release.cluster.shared::cluster.b64 _, [%0];"
                     :: "r"(r_b1) : "memory");
    }

    unsigned par0 = 0u, par1 = 0u;

    // prefetch gate term for step 0 (phase-2 threads)
    const int gcol2 = (tid >> 5) * 256 + (int)rank * 32 + (tid & 31);
    float gt = (tid < 128) ? g_G[gcol2] : 0.f;

    for (int t = 0; t < NB; t++) {
        const int rb = (t + 1) & 1;      // buffer holding h_{t-1}
        const int wb = t & 1;            // buffer receiving h_t
        const int pp = t & 1;            // s_part parity

        { // wait ONLY for my source CTA's push of h_{t-1}
            const unsigned a = rb ? w_b1 : w_b0;
            const unsigned ph = rb ? par1 : par0;
            unsigned done;
            asm volatile(
                "{\n\t.reg .pred p;\n\t"
                "mbarrier.try_wait.parity.acquire.cluster.shared::cta.b64 p, [%1], %2;\n\t"
                "selp.b32 %0, 1, 0, p;\n\t}"
                : "=r"(done) : "r"(a), "r"(ph) : "memory");
            if (!done) {
                asm volatile(
                    "{\n\t.reg .pred P1;\n\t"
                    "WLB_%=:\n\t"
                    "mbarrier.try_wait.parity.acquire.cluster.shared::cta.b64 P1, [%0], %1, 0x989680;\n\t"
                    "@P1 bra.uni WDB_%=;\n\t"
                    "bra.uni WLB_%=;\n\t"
                    "WDB_%=:\n\t}"
                    :: "r"(a), "r"(ph) : "memory");
            }
            if (rb) par1 ^= 1u; else par0 ^= 1u;
        }

        // ---- GEMV phase 1: 4 cols x 16 k per thread, packed f32x2 ----
        {
            const unsigned long long* hp =
                (const unsigned long long*)&s_hb[rb][k0];
            unsigned long long a0 = 0ULL, a1 = 0ULL, a2 = 0ULL, a3 = 0ULL;
            #pragma unroll
            for (int p = 0; p < 8; p++) {
                const unsigned long long h2 = hp[p];
                a0 = fma2u(wv[0][p], h2, a0);
                a1 = fma2u(wv[1][p], h2, a1);
                a2 = fma2u(wv[2][p], h2, a2);
                a3 = fma2u(wv[3][p], h2, a3);
            }
            float2 f0, f1, f2, f3;
            asm("mov.b64 {%0,%1}, %2;" : "=f"(f0.x), "=f"(f0.y) : "l"(a0));
            asm("mov.b64 {%0,%1}, %2;" : "=f"(f1.x), "=f"(f1.y) : "l"(a1));
            asm("mov.b64 {%0,%1}, %2;" : "=f"(f2.x), "=f"(f2.y) : "l"(a2));
            asm("mov.b64 {%0,%1}, %2;" : "=f"(f3.x), "=f"(f3.y) : "l"(a3));
            float4 p4;
            p4.x = f0.x + f0.y; p4.y = f1.x + f1.y;
            p4.z = f2.x + f2.y; p4.w = f3.x + f3.y;
            *(float4*)&s_part[pp][kw * 128 + g * 4] = p4;
        }
        __syncthreads();   // all 512: partials of step t visible

        // ---- phase2 + cell: warps 0-3 only; warps 4-15 go to next wait ----
        if (tid < 128) {
            float v[16];
            #pragma unroll
            for (int k2 = 0; k2 < 16; k2++)
                v[k2] = s_part[pp][k2 * 128 + tid];
            const float s =
                (((v[0] + v[1]) + (v[2] + v[3])) + ((v[4] + v[5]) + (v[6] + v[7]))) +
                (((v[8] + v[9]) + (v[10] + v[11])) + ((v[12] + v[13]) + (v[14] + v[15]))) + gt;
            s_z[tid] = s;
            if (t + 1 < NB) gt = g_G[(size_t)(t + 1) * 1024 + gcol2];

            asm volatile("bar.sync 1, 128;" ::: "memory");

            if (tid < 32) {
                const float zi = s_z[tid];
                const float zf = s_z[32 + tid];
                const float zc = s_z[64 + tid];
                const float zo = s_z[96 + tid];

                float s1 = zc, s2 = zc * zc;
                s1 += __shfl_xor_sync(0xffffffffu, s1, 1);  s2 += __shfl_xor_sync(0xffffffffu, s2, 1);
                s1 += __shfl_xor_sync(0xffffffffu, s1, 2);  s2 += __shfl_xor_sync(0xffffffffu, s2, 2);
                s1 += __shfl_xor_sync(0xffffffffu, s1, 4);  s2 += __shfl_xor_sync(0xffffffffu, s2, 4);
                float mean = s1 * 0.125f;
                float var  = s2 * 0.125f - mean * mean;
                const float ecc = zc * sigf(vl * zc) * rsqrtf(var + 1e-5f) * gl + bl;

                cst = sigf(zf) * cst + sigf(zi) * ecc;

                s1 = cst; s2 = cst * cst;
                s1 += __shfl_xor_sync(0xffffffffu, s1, 1);  s2 += __shfl_xor_sync(0xffffffffu, s2, 1);
                s1 += __shfl_xor_sync(0xffffffffu, s1, 2);  s2 += __shfl_xor_sync(0xffffffffu, s2, 2);
                s1 += __shfl_xor_sync(0xffffffffu, s1, 4);  s2 += __shfl_xor_sync(0xffffffffu, s2, 4);
                mean = s1 * 0.125f;
                var  = s2 * 0.125f - mean * mean;
                const float ecn = cst * sigf(vl * cst) * rsqrtf(var + 1e-5f) * gl + bl;

                const float h = sigf(zo) * ecn;
                s_hout[tid] = h;
                __syncwarp();

                // push h_t: lane d -> dest CTA d (8 x st.v4 + 1 release-arrive)
                if (tid < 8) {
                    const unsigned rh  = wb ? r_h1 : r_h0;
                    const unsigned rbb = wb ? r_b1 : r_b0;
                    #pragma unroll
                    for (int i = 0; i < 8; i++) {
                        const float4 hv4 = *(const float4*)&s_hout[i * 4];
                        asm volatile("st.shared::cluster.v4.f32 [%0], {%1,%2,%3,%4};"
                                     :: "r"(rh + i * 16), "f"(hv4.x), "f"(hv4.y), "f"(hv4.z), "f"(hv4.w)
                                     : "memory");
                    }
                    asm volatile("mbarrier.arrive.release.cluster.shared::cluster.b64 _, [%0];"
                                 :: "r"(rbb) : "memory");
                }
                g_H[(size_t)t * 256 + rank * 32 + tid] = h;
            }
        }
    }

    asm volatile("barrier.cluster.arrive.aligned;" ::: "memory");
    asm volatile("barrier.cluster.wait.aligned;"   ::: "memory");
}

// ===== Kernel C: dense_0 + evonorm -> bf16 hi/lo split (g_Ah/g_Al) ==========
__global__ __launch_bounds__(256) void kC(
    const float* __restrict__ Wd0, const float* __restrict__ vd,
    const float* __restrict__ gd,  const float* __restrict__ bd)
{
    __shared__ float sm1[16 * 256];
    __shared__ float sm2[16 * 256];
    const int tid = threadIdx.x;
    const int r0  = blockIdx.x * 16;

    const float4* src = (const float4*)(g_H + (size_t)r0 * 256);
    for (int i = tid; i < 1024; i += 256)
        ((float4*)sm1)[i] = src[i];
    __syncthreads();

    const int j = tid;
    float acc[16];
    #pragma unroll
    for (int r = 0; r < 16; r++) acc[r] = 0.f;
    for (int k4 = 0; k4 < 64; k4++) {
        const int k = k4 * 4;
        const float w0 = Wd0[(k+0)*256 + j];
        const float w1 = Wd0[(k+1)*256 + j];
        const float w2 = Wd0[(k+2)*256 + j];
        const float w3 = Wd0[(k+3)*256 + j];
        #pragma unroll
        for (int r = 0; r < 16; r++) {
            const float4 x = *(const float4*)&sm1[r * 256 + k];
            acc[r] += x.x*w0 + x.y*w1 + x.z*w2 + x.w*w3;
        }
    }
    #pragma unroll
    for (int r = 0; r < 16; r++) sm2[r * 256 + j] = acc[r];
    __syncthreads();

    const float v = vd[j], g = gd[j], bb = bd[j];
    for (int r = 0; r < 16; r++) {
        const float* row = &sm2[r * 256 + (j & ~7)];
        float s1 = 0.f, s2 = 0.f;
        #pragma unroll
        for (int e = 0; e < 8; e++) { float t = row[e]; s1 += t; s2 += t * t; }
        const float mean = s1 * 0.125f;
        const float var  = s2 * 0.125f - mean * mean;
        const float x = sm2[r * 256 + j];
        const float y = x * sigf(v * x) * rsqrtf(var + 1e-5f) * g + bb;
        const __nv_bfloat16 hi = __float2bfloat16(y);
        const __nv_bfloat16 lo = __float2bfloat16(y - __bfloat162float(hi));
        g_Ah[(size_t)(r0 + r) * 256 + j] = hi;
        g_Al[(size_t)(r0 + r) * 256 + j] = lo;
    }
}

// ===== Kernel D: HMMA bf16 3-split GEMM, B smem-resident, A streamed ========
// CTA owns a 128-col B slice (all K, 128KB smem); 8 row tiles, A chunks
// double-buffered and software-pipelined ACROSS tiles (epilogue overlaps
// the next tile's A loads). Grid: x = 2 row halves, y = 516 col tiles.
#define KDB_SZ    131072
#define KDA_STAGE 32768
#define KD_SMEM   (KDB_SZ + 2 * KDA_STAGE)   // 196608

__device__ __forceinline__ void kd_loadB(uint32_t SB, int n0, int tid)
{
    #pragma unroll
    for (int c = 0; c < 4; c++) {
        #pragma unroll
        for (int sp = 0; sp < 2; sp++) {
            const __nv_bfloat16* gB = sp ? g_Bl : g_Bh;
            const uint32_t db = SB + c * 32768u + sp * 16384u;
            #pragma unroll
            for (int i = 0; i < 4; i++) {
                const int g2 = tid + i * 256;
                const int row = g2 >> 3, j = g2 & 7;
                CP_ASYNC16(db + SWZ(row * 128 + j * 16),
                           gB + (size_t)(n0 + row) * 256 + c * 64 + j * 8);
            }
        }
    }
    CP_COMMIT();
}

__device__ __forceinline__ void kd_loadA(uint32_t stage, int m0, int koff, int tid)
{
    #pragma unroll
    for (int sp = 0; sp < 2; sp++) {
        const __nv_bfloat16* gA = sp ? g_Al : g_Ah;
        const uint32_t db = stage + sp * 16384u;
        #pragma unroll
        for (int i = 0; i < 4; i++) {
            const int g2 = tid + i * 256;
            const int row = g2 >> 3, j = g2 & 7;
            CP_ASYNC16(db + SWZ(row * 128 + j * 16),
                       gA + (size_t)(m0 + row) * 256 + koff + j * 8);
        }
    }
    CP_COMMIT();
}

__device__ __forceinline__ void kd_compute(uint32_t Astage, uint32_t SB, int blk,
                                           uint32_t a_row, uint32_t a_kb,
                                           uint32_t b_row, uint32_t b_kb,
                                           float acc[4][4][4])
{
    #pragma unroll
    for (int split = 0; split < 3; split++) {
        const uint32_t Abase = Astage + (split == 2 ? 16384u : 0u);
        const uint32_t Bbase = SB + blk * 32768u + (split == 1 ? 16384u : 0u);
        #pragma unroll
        for (int ks = 0; ks < 4; ks++) {
            const uint32_t kk2 = (uint32_t)ks * 32;
            uint32_t af[4][4];
            #pragma unroll
            for (int mb = 0; mb < 4; mb++) {
                const uint32_t addr = Abase + SWZ((a_row + mb * 16) * 128 + kk2 + a_kb);
                LDSM_X4(af[mb][0], af[mb][1], af[mb][2], af[mb][3], addr);
            }
            uint32_t bfr[2][4];
            #pragma unroll
            for (int nb2 = 0; nb2 < 2; nb2++) {
                const uint32_t addr = Bbase + SWZ((b_row + nb2 * 16) * 128 + kk2 + b_kb);
                LDSM_X4(bfr[nb2][0], bfr[nb2][1], bfr[nb2][2], bfr[nb2][3], addr);
            }
            #pragma unroll
            for (int mb = 0; mb < 4; mb++) {
                MMA16816(acc[mb][0], af[mb], bfr[0][0], bfr[0][1]);
                MMA16816(acc[mb][1], af[mb], bfr[0][2], bfr[0][3]);
                MMA16816(acc[mb][2], af[mb], bfr[1][0], bfr[1][1]);
                MMA16816(acc[mb][3], af[mb], bfr[1][2], bfr[1][3]);
            }
        }
    }
}

__global__ void __launch_bounds__(256)
kD(const float* __restrict__ bout, float* __restrict__ out)
{
    extern __shared__ __align__(1024) char smem[];
    const uint32_t SB  = smem_u32(smem);
    const uint32_t SA0 = SB + KDB_SZ;
    const uint32_t SA1 = SA0 + KDA_STAGE;
    const int tid = threadIdx.x;
    const int wid = tid >> 5, lane = tid & 31;
    const int warp_m = wid & 1;
    const int warp_n = wid >> 1;
    const int n0 = blockIdx.y * 128;

    const uint32_t a_row = warp_m * 64 + (lane & 15);
    const uint32_t a_kb  = (uint32_t)(lane >> 4) * 16;
    const uint32_t b_row = warp_n * 32 + (lane & 7) + ((lane >> 4) & 1) * 8;
    const uint32_t b_kb  = (uint32_t)((lane >> 3) & 1) * 16;

    kd_loadB(SB, n0, tid);                              // group B
    {
        const int m0f = blockIdx.x * 8 * 128;
        kd_loadA(SA0, m0f, 0,  tid);                    // tile0 chunk0
        kd_loadA(SA1, m0f, 64, tid);                    // tile0 chunk1
    }

    for (int r = 0; r < 8; r++) {
        const int m0c = (blockIdx.x * 8 + r) * 128;
        const int m0n = (blockIdx.x * 8 + (r < 7 ? r + 1 : r)) * 128;

        float acc[4][4][4];
        #pragma unroll
        for (int i = 0; i < 4; i++)
            #pragma unroll
            for (int j = 0; j < 4; j++)
                #pragma unroll
                for (int qq = 0; qq < 4; qq++) acc[i][j][qq] = 0.f;

        // Invariant at loop head: 2 groups pending (cur chunk0 -> SA0,
        // cur chunk1 -> SA1). WAIT1 before each consume.
        CP_WAIT1();  __syncthreads();       // chunk0 (and B on r==0) ready
        kd_compute(SA0, SB, 0, a_row, a_kb, b_row, b_kb, acc);
        __syncthreads();
        kd_loadA(SA0, m0c, 128, tid);       // chunk2
        CP_WAIT1();  __syncthreads();       // chunk1 ready
        kd_compute(SA1, SB, 1, a_row, a_kb, b_row, b_kb, acc);
        __syncthreads();
        kd_loadA(SA1, m0c, 192, tid);       // chunk3
        CP_WAIT1();  __syncthreads();       // chunk2 ready
        kd_compute(SA0, SB, 2, a_row, a_kb, b_row, b_kb, acc);
        __syncthreads();
        kd_loadA(SA0, m0n, 0, tid);         // next tile chunk0
        CP_WAIT1();  __syncthreads();       // chunk3 ready
        kd_compute(SA1, SB, 3, a_row, a_kb, b_row, b_kb, acc);
        __syncthreads();
        kd_loadA(SA1, m0n, 64, tid);        // next tile chunk1

        // ---- epilogue (overlaps in-flight next-tile loads) ----
        #pragma unroll
        for (int nb = 0; nb < 4; nb++) {
            const int col = n0 + warp_n * 32 + nb * 8 + (lane & 3) * 2;
            const float2 bb = *(const float2*)&bout[col];
            #pragma unroll
            for (int mb = 0; mb < 4; mb++) {
                const int row = m0c + warp_m * 64 + mb * 16 + (lane >> 2);
                float2 v0, v1;
                v0.x = acc[mb][nb][0] + bb.x;  v0.y = acc[mb][nb][1] + bb.y;
                v1.x = acc[mb][nb][2] + bb.x;  v1.y = acc[mb][nb][3] + bb.y;
                *(float2*)&out[(size_t)row * NPAR + col]       = v0;
                *(float2*)&out[(size_t)(row + 8) * NPAR + col] = v1;
            }
        }
    }
    CP_WAIT0();   // drain trailing (duplicate) loads before exit
}

// ============================================================================
extern "C" void kernel_launch(void* const* d_in, const int* in_sizes, int n_in,
                              void* d_out, int out_size)
{
    const float* actions = (const float*)d_in[0];
    const float* obs     = (const float*)d_in[1];
    const float* Wci     = (const float*)d_in[2];
    const float* vci     = (const float*)d_in[3];
    const float* gci     = (const float*)d_in[4];
    const float* bci     = (const float*)d_in[5];
    const float* Wcl     = (const float*)d_in[6];
    const float* bcl     = (const float*)d_in[7];
    const float* Win     = (const float*)d_in[8];
    const float* vin     = (const float*)d_in[9];
    const float* gin     = (const float*)d_in[10];
    const float* bin     = (const float*)d_in[11];
    const float* Wk      = (const float*)d_in[12];
    const float* Wr      = (const float*)d_in[13];
    const float* vl      = (const float*)d_in[14];
    const float* gl      = (const float*)d_in[15];
    const float* bl      = (const float*)d_in[16];
    const float* Wd0     = (const float*)d_in[17];
    const float* vd0     = (const float*)d_in[18];
    const float* gd0     = (const float*)d_in[19];
    const float* bd0     = (const float*)d_in[20];
    const float* Wout    = (const float*)d_in[21];
    const float* bout    = (const float*)d_in[22];
    float* out = (float*)d_out;

    kWA<<<KWA_NW + 128, 256>>>(Wout, actions, obs, Wci, vci, gci, bci, Wcl, bcl,
                               Win, vin, gin, bin, Wk);
    kB<<<8, 512>>>(Wr, vl, gl, bl);
    kC<<<128, 256>>>(Wd0, vd0, gd0, bd0);

    cudaFuncSetAttribute(kD, cudaFuncAttributeMaxDynamicSharedMemorySize, KD_SMEM);
    dim3 gD(2, NPAR / 128);   // x = row halves, y = col tiles (516)
    kD<<<gD, 256, KD_SMEM>>>(bout, out);
}